// round 11
// baseline (speedup 1.0000x reference)
#include <cuda_runtime.h>
#include <cuda_bf16.h>
#include <cstdint>

#define NROWS 8192
#define KDIM  128
#define GAMMA_F 0.005f   // 1/(2*10^2)

#define TILE 128
#define THREADS 256

// SMEM: padded bf16 tiles, row stride 272 bytes (128 bf16 = 256B + 16B pad)
#define ROW_BYTES 272
#define TILE_BYTES (TILE * ROW_BYTES)          // 34816
#define SMEM_A  0
#define SMEM_B  TILE_BYTES                      // 34816
#define SMEM_N1 (2 * TILE_BYTES)                // 69632
#define SMEM_N2 (SMEM_N1 + TILE * 4)            // 70144
#define SMEM_TOTAL (SMEM_N2 + TILE * 4)         // 70656

static __device__ __forceinline__ uint32_t smem_u32(const void* p) {
    uint32_t a;
    asm("{ .reg .u64 t; cvta.to.shared.u64 t, %1; cvt.u32.u64 %0, t; }"
        : "=r"(a) : "l"(p));
    return a;
}

static __device__ __forceinline__ void ldsm_x4(uint32_t& r0, uint32_t& r1,
                                               uint32_t& r2, uint32_t& r3,
                                               uint32_t addr) {
    asm volatile("ldmatrix.sync.aligned.m8n8.x4.shared.b16 {%0,%1,%2,%3}, [%4];"
                 : "=r"(r0), "=r"(r1), "=r"(r2), "=r"(r3) : "r"(addr));
}

static __device__ __forceinline__ void mma_16816(float* d,
                                                 const uint32_t* a,
                                                 uint32_t b0, uint32_t b1) {
    asm volatile(
        "mma.sync.aligned.m16n8k16.row.col.f32.bf16.bf16.f32 "
        "{%0,%1,%2,%3}, {%4,%5,%6,%7}, {%8,%9}, {%0,%1,%2,%3};"
        : "+f"(d[0]), "+f"(d[1]), "+f"(d[2]), "+f"(d[3])
        : "r"(a[0]), "r"(a[1]), "r"(a[2]), "r"(a[3]), "r"(b0), "r"(b1));
}

// ---------------- fused kernel (R4 structure + in-load norms) ----------------
__global__ void __launch_bounds__(THREADS)
rbf_mma_kernel(const float* __restrict__ x1,
               const float* __restrict__ x2,
               float* __restrict__ out)
{
    extern __shared__ char smem[];
    uint32_t sbase = smem_u32(smem);
    int tid = threadIdx.x;
    int wid = tid >> 5;
    int lane = tid & 31;

    int rowBase = blockIdx.y * TILE;
    int colBase = blockIdx.x * TILE;

    float* sn1 = reinterpret_cast<float*>(smem + SMEM_N1);
    float* sn2 = reinterpret_cast<float*>(smem + SMEM_N2);

    // ---- load tiles fp32 -> bf16 into padded SMEM, fused norm reduction ----
    // Each warp owns one row per iteration: row = 8*it + wid (same LDG pattern
    // as R4, where idx>>5 == 8*it + wid). Norms reduced via xor-shfl tree.
    {
        const float4* a4 = reinterpret_cast<const float4*>(x1 + (size_t)rowBase * KDIM);
        const float4* b4 = reinterpret_cast<const float4*>(x2 + (size_t)colBase * KDIM);
        #pragma unroll
        for (int it = 0; it < (TILE * 32) / THREADS; ++it) {
            int row = 8 * it + wid;
            int c4  = lane;
            float4 va = a4[(size_t)row * 32 + c4];
            float4 vb = b4[(size_t)row * 32 + c4];

            float sa = va.x * va.x + va.y * va.y + va.z * va.z + va.w * va.w;
            float sb = vb.x * vb.x + vb.y * vb.y + vb.z * vb.z + vb.w * vb.w;
            #pragma unroll
            for (int m = 16; m > 0; m >>= 1) {
                sa += __shfl_xor_sync(0xFFFFFFFFu, sa, m);
                sb += __shfl_xor_sync(0xFFFFFFFFu, sb, m);
            }
            if (lane == 0) { sn1[row] = sa; sn2[row] = sb; }

            __nv_bfloat162 a0 = __floats2bfloat162_rn(va.x, va.y);
            __nv_bfloat162 a1 = __floats2bfloat162_rn(va.z, va.w);
            __nv_bfloat162 b0 = __floats2bfloat162_rn(vb.x, vb.y);
            __nv_bfloat162 b1 = __floats2bfloat162_rn(vb.z, vb.w);
            uint32_t off = (uint32_t)row * ROW_BYTES + (uint32_t)c4 * 8;
            *reinterpret_cast<uint2*>(smem + SMEM_A + off) =
                make_uint2(*reinterpret_cast<uint32_t*>(&a0), *reinterpret_cast<uint32_t*>(&a1));
            *reinterpret_cast<uint2*>(smem + SMEM_B + off) =
                make_uint2(*reinterpret_cast<uint32_t*>(&b0), *reinterpret_cast<uint32_t*>(&b1));
        }
    }
    __syncthreads();

    // ---- mma mainloop: warp grid 2(M) x 4(N); each warp 64x32 ----
    int mw = wid >> 2;       // 0..1
    int nw = wid & 3;        // 0..3

    float acc[4][4][4];      // [mi][ni][reg]
    #pragma unroll
    for (int mi = 0; mi < 4; ++mi)
        #pragma unroll
        for (int ni = 0; ni < 4; ++ni)
            #pragma unroll
            for (int r = 0; r < 4; ++r) acc[mi][ni][r] = 0.0f;

    uint32_t lrow  = lane & 15;
    uint32_t lhalf = (lane >> 4) * 16;   // byte offset of k-half

    #pragma unroll
    for (int ks = 0; ks < 8; ++ks) {
        uint32_t koff = (uint32_t)ks * 32 + lhalf;

        uint32_t af[4][4];
        #pragma unroll
        for (int mi = 0; mi < 4; ++mi) {
            uint32_t row = (uint32_t)(mw * 64 + mi * 16) + lrow;
            ldsm_x4(af[mi][0], af[mi][1], af[mi][2], af[mi][3],
                    sbase + SMEM_A + row * ROW_BYTES + koff);
        }
        uint32_t bf[2][4];
        #pragma unroll
        for (int nj = 0; nj < 2; ++nj) {
            uint32_t row = (uint32_t)(nw * 32 + nj * 16) + lrow;
            ldsm_x4(bf[nj][0], bf[nj][1], bf[nj][2], bf[nj][3],
                    sbase + SMEM_B + row * ROW_BYTES + koff);
        }
        #pragma unroll
        for (int mi = 0; mi < 4; ++mi) {
            #pragma unroll
            for (int ni = 0; ni < 4; ++ni) {
                int nj = ni >> 1, sub = ni & 1;
                mma_16816(acc[mi][ni], af[mi], bf[nj][sub], bf[nj][sub + 2]);
            }
        }
    }

    // ---- R4 epilogue: exp directly on acc, STG.64, no cross-lane deps ----
    {
        int qr = lane >> 2;          // 0..7
        int qc = (lane & 3) * 2;     // 0,2,4,6

        #pragma unroll
        for (int mi = 0; mi < 4; ++mi) {
            int row0 = mw * 64 + mi * 16 + qr;       // rows row0 and row0+8
            float n1a = sn1[row0];
            float n1b = sn1[row0 + 8];
            float* out0 = out + (size_t)(rowBase + row0) * NROWS + colBase;
            float* out1 = out0 + (size_t)8 * NROWS;
            #pragma unroll
            for (int ni = 0; ni < 4; ++ni) {
                int col = nw * 32 + ni * 8 + qc;
                float n2a = sn2[col];
                float n2b = sn2[col + 1];
                float2 oa, ob;
                oa.x = __expf(-GAMMA_F * (n1a + n2a - 2.0f * acc[mi][ni][0]));
                oa.y = __expf(-GAMMA_F * (n1a + n2b - 2.0f * acc[mi][ni][1]));
                ob.x = __expf(-GAMMA_F * (n1b + n2a - 2.0f * acc[mi][ni][2]));
                ob.y = __expf(-GAMMA_F * (n1b + n2b - 2.0f * acc[mi][ni][3]));
                *reinterpret_cast<float2*>(out0 + col) = oa;
                *reinterpret_cast<float2*>(out1 + col) = ob;
            }
        }
    }
}

// ---------------- launch ----------------
extern "C" void kernel_launch(void* const* d_in, const int* in_sizes, int n_in,
                              void* d_out, int out_size)
{
    const float* x1 = (const float*)d_in[0];
    const float* x2 = (const float*)d_in[1];
    float* out = (float*)d_out;

    cudaFuncSetAttribute(rbf_mma_kernel,
                         cudaFuncAttributeMaxDynamicSharedMemorySize, SMEM_TOTAL);
    cudaFuncSetAttribute(rbf_mma_kernel,
                         cudaFuncAttributePreferredSharedMemoryCarveout, 100);

    dim3 grid(NROWS / TILE, NROWS / TILE);   // 64 x 64
    rbf_mma_kernel<<<grid, THREADS, SMEM_TOTAL>>>(x1, x2, out);
}

// round 12
// speedup vs baseline: 1.0150x; 1.0150x over previous
#include <cuda_runtime.h>
#include <cuda_bf16.h>
#include <cstdint>

#define NROWS 8192
#define KDIM  128
#define GAMMA_F 0.005f   // 1/(2*10^2)

#define TILE_M 64
#define TILE_N 128
#define THREADS 256

// SMEM: padded bf16 tiles, row stride 272 bytes (128 bf16 = 256B + 16B pad)
#define ROW_BYTES 272
#define SMEM_A  0
#define SMEM_B  (TILE_M * ROW_BYTES)                    // 17408
#define SMEM_N1 (SMEM_B + TILE_N * ROW_BYTES)           // 52224
#define SMEM_N2 (SMEM_N1 + TILE_M * 4)                  // 52480
#define SMEM_TOTAL (SMEM_N2 + TILE_N * 4)               // 52992

__device__ float g_n1[NROWS];
__device__ float g_n2[NROWS];

static __device__ __forceinline__ uint32_t smem_u32(const void* p) {
    uint32_t a;
    asm("{ .reg .u64 t; cvta.to.shared.u64 t, %1; cvt.u32.u64 %0, t; }"
        : "=r"(a) : "l"(p));
    return a;
}

static __device__ __forceinline__ void ldsm_x4(uint32_t& r0, uint32_t& r1,
                                               uint32_t& r2, uint32_t& r3,
                                               uint32_t addr) {
    asm volatile("ldmatrix.sync.aligned.m8n8.x4.shared.b16 {%0,%1,%2,%3}, [%4];"
                 : "=r"(r0), "=r"(r1), "=r"(r2), "=r"(r3) : "r"(addr));
}

static __device__ __forceinline__ void mma_16816(float* d,
                                                 const uint32_t* a,
                                                 uint32_t b0, uint32_t b1) {
    asm volatile(
        "mma.sync.aligned.m16n8k16.row.col.f32.bf16.bf16.f32 "
        "{%0,%1,%2,%3}, {%4,%5,%6,%7}, {%8,%9}, {%0,%1,%2,%3};"
        : "+f"(d[0]), "+f"(d[1]), "+f"(d[2]), "+f"(d[3])
        : "r"(a[0]), "r"(a[1]), "r"(a[2]), "r"(a[3]), "r"(b0), "r"(b1));
}

// ---------------- norms kernel (proven) ----------------
__global__ void rbf_norms_kernel(const float* __restrict__ x1,
                                 const float* __restrict__ x2)
{
    int warp = (blockIdx.x * blockDim.x + threadIdx.x) >> 5;
    int lane = threadIdx.x & 31;
    if (warp >= 2 * NROWS) return;
    const float* src = (warp < NROWS) ? x1 : x2;
    float* dst = (warp < NROWS) ? g_n1 : g_n2;
    int row = warp & (NROWS - 1);
    float4 v = reinterpret_cast<const float4*>(src + (size_t)row * KDIM)[lane];
    float s = v.x * v.x + v.y * v.y + v.z * v.z + v.w * v.w;
    #pragma unroll
    for (int m = 16; m > 0; m >>= 1)
        s += __shfl_xor_sync(0xFFFFFFFFu, s, m);
    if (lane == 0) dst[row] = s;
}

// ---------------- main kernel: 64x128 CTA tile, 8 warps, warp tile 32x32 ----
__global__ void __launch_bounds__(THREADS)
rbf_mma_kernel(const float* __restrict__ x1,
               const float* __restrict__ x2,
               float* __restrict__ out)
{
    extern __shared__ char smem[];
    uint32_t sbase = smem_u32(smem);
    int tid = threadIdx.x;
    int wid = tid >> 5;
    int lane = tid & 31;

    int rowBase = blockIdx.y * TILE_M;
    int colBase = blockIdx.x * TILE_N;

    // ---- load tiles fp32 -> bf16 into padded SMEM (R4 pattern, no fusion) ----
    {
        const float4* a4 = reinterpret_cast<const float4*>(x1 + (size_t)rowBase * KDIM);
        const float4* b4 = reinterpret_cast<const float4*>(x2 + (size_t)colBase * KDIM);
        // A: 64 rows x 32 float4 = 2048 -> 8 iterations
        #pragma unroll
        for (int it = 0; it < (TILE_M * 32) / THREADS; ++it) {
            int row = 8 * it + wid;
            float4 v = a4[(size_t)row * 32 + lane];
            __nv_bfloat162 p0 = __floats2bfloat162_rn(v.x, v.y);
            __nv_bfloat162 p1 = __floats2bfloat162_rn(v.z, v.w);
            uint32_t off = (uint32_t)row * ROW_BYTES + (uint32_t)lane * 8;
            *reinterpret_cast<uint2*>(smem + SMEM_A + off) =
                make_uint2(*reinterpret_cast<uint32_t*>(&p0), *reinterpret_cast<uint32_t*>(&p1));
        }
        // B: 128 rows x 32 float4 = 4096 -> 16 iterations
        #pragma unroll
        for (int it = 0; it < (TILE_N * 32) / THREADS; ++it) {
            int row = 8 * it + wid;
            float4 v = b4[(size_t)row * 32 + lane];
            __nv_bfloat162 p0 = __floats2bfloat162_rn(v.x, v.y);
            __nv_bfloat162 p1 = __floats2bfloat162_rn(v.z, v.w);
            uint32_t off = (uint32_t)row * ROW_BYTES + (uint32_t)lane * 8;
            *reinterpret_cast<uint2*>(smem + SMEM_B + off) =
                make_uint2(*reinterpret_cast<uint32_t*>(&p0), *reinterpret_cast<uint32_t*>(&p1));
        }
        if (tid < TILE_M) {
            reinterpret_cast<float*>(smem + SMEM_N1)[tid] = g_n1[rowBase + tid];
        } else if (tid < TILE_M + TILE_N) {
            reinterpret_cast<float*>(smem + SMEM_N2)[tid - TILE_M] =
                g_n2[colBase + (tid - TILE_M)];
        }
    }
    __syncthreads();

    // ---- mma mainloop: warp grid 2(M) x 4(N); each warp 32x32 ----
    int mw = wid >> 2;       // 0..1  (M offset 32 per)
    int nw = wid & 3;        // 0..3  (N offset 32 per)

    float acc[2][4][4];      // [mi][ni][reg] : 32 floats
    #pragma unroll
    for (int mi = 0; mi < 2; ++mi)
        #pragma unroll
        for (int ni = 0; ni < 4; ++ni)
            #pragma unroll
            for (int r = 0; r < 4; ++r) acc[mi][ni][r] = 0.0f;

    uint32_t lrow  = lane & 15;
    uint32_t lhalf = (lane >> 4) * 16;   // byte offset of k-half

    #pragma unroll
    for (int ks = 0; ks < 8; ++ks) {
        uint32_t koff = (uint32_t)ks * 32 + lhalf;

        uint32_t af[2][4];
        #pragma unroll
        for (int mi = 0; mi < 2; ++mi) {
            uint32_t row = (uint32_t)(mw * 32 + mi * 16) + lrow;
            ldsm_x4(af[mi][0], af[mi][1], af[mi][2], af[mi][3],
                    sbase + SMEM_A + row * ROW_BYTES + koff);
        }
        uint32_t bf[2][4];
        #pragma unroll
        for (int nj = 0; nj < 2; ++nj) {
            uint32_t row = (uint32_t)(nw * 32 + nj * 16) + lrow;
            ldsm_x4(bf[nj][0], bf[nj][1], bf[nj][2], bf[nj][3],
                    sbase + SMEM_B + row * ROW_BYTES + koff);
        }
        #pragma unroll
        for (int mi = 0; mi < 2; ++mi) {
            #pragma unroll
            for (int ni = 0; ni < 4; ++ni) {
                int nj = ni >> 1, sub = ni & 1;
                mma_16816(acc[mi][ni], af[mi], bf[nj][sub], bf[nj][sub + 2]);
            }
        }
    }

    // ---- R4 epilogue: exp directly on acc, STG.64, no cross-lane deps ----
    {
        const float* sn1 = reinterpret_cast<const float*>(smem + SMEM_N1);
        const float* sn2 = reinterpret_cast<const float*>(smem + SMEM_N2);
        int qr = lane >> 2;          // 0..7
        int qc = (lane & 3) * 2;     // 0,2,4,6

        #pragma unroll
        for (int mi = 0; mi < 2; ++mi) {
            int row0 = mw * 32 + mi * 16 + qr;       // rows row0 and row0+8
            float n1a = sn1[row0];
            float n1b = sn1[row0 + 8];
            float* out0 = out + (size_t)(rowBase + row0) * NROWS + colBase;
            float* out1 = out0 + (size_t)8 * NROWS;
            #pragma unroll
            for (int ni = 0; ni < 4; ++ni) {
                int col = nw * 32 + ni * 8 + qc;
                float n2a = sn2[col];
                float n2b = sn2[col + 1];
                float2 oa, ob;
                oa.x = __expf(-GAMMA_F * (n1a + n2a - 2.0f * acc[mi][ni][0]));
                oa.y = __expf(-GAMMA_F * (n1a + n2b - 2.0f * acc[mi][ni][1]));
                ob.x = __expf(-GAMMA_F * (n1b + n2a - 2.0f * acc[mi][ni][2]));
                ob.y = __expf(-GAMMA_F * (n1b + n2b - 2.0f * acc[mi][ni][3]));
                *reinterpret_cast<float2*>(out0 + col) = oa;
                *reinterpret_cast<float2*>(out1 + col) = ob;
            }
        }
    }
}

// ---------------- launch ----------------
extern "C" void kernel_launch(void* const* d_in, const int* in_sizes, int n_in,
                              void* d_out, int out_size)
{
    const float* x1 = (const float*)d_in[0];
    const float* x2 = (const float*)d_in[1];
    float* out = (float*)d_out;

    cudaFuncSetAttribute(rbf_mma_kernel,
                         cudaFuncAttributeMaxDynamicSharedMemorySize, SMEM_TOTAL);
    cudaFuncSetAttribute(rbf_mma_kernel,
                         cudaFuncAttributePreferredSharedMemoryCarveout, 100);

    rbf_norms_kernel<<<(2 * NROWS) / 8, 256>>>(x1, x2);

    dim3 grid(NROWS / TILE_N, NROWS / TILE_M);   // 64 x 128 = 8192
    rbf_mma_kernel<<<grid, THREADS, SMEM_TOTAL>>>(x1, x2, out);
}

// round 13
// speedup vs baseline: 1.0855x; 1.0694x over previous
#include <cuda_runtime.h>
#include <cuda_bf16.h>
#include <cstdint>

#define NROWS 8192
#define KDIM  128
#define GAMMA_F 0.005f   // 1/(2*10^2)

#define TILE 128
#define THREADS 256

// SMEM: padded bf16 tiles, row stride 272 bytes (128 bf16 = 256B + 16B pad)
#define ROW_BYTES 272
#define TILE_BYTES (TILE * ROW_BYTES)          // 34816
#define SMEM_A  0
#define SMEM_B  TILE_BYTES                      // 34816
#define SMEM_N1 (2 * TILE_BYTES)                // 69632
#define SMEM_N2 (SMEM_N1 + TILE * 4)            // 70144
#define SMEM_TOTAL (SMEM_N2 + TILE * 4)         // 70656

__device__ float g_n1[NROWS];
__device__ float g_n2[NROWS];

static __device__ __forceinline__ uint32_t smem_u32(const void* p) {
    uint32_t a;
    asm("{ .reg .u64 t; cvta.to.shared.u64 t, %1; cvt.u32.u64 %0, t; }"
        : "=r"(a) : "l"(p));
    return a;
}

static __device__ __forceinline__ void ldsm_x4(uint32_t& r0, uint32_t& r1,
                                               uint32_t& r2, uint32_t& r3,
                                               uint32_t addr) {
    asm volatile("ldmatrix.sync.aligned.m8n8.x4.shared.b16 {%0,%1,%2,%3}, [%4];"
                 : "=r"(r0), "=r"(r1), "=r"(r2), "=r"(r3) : "r"(addr));
}

static __device__ __forceinline__ void mma_16816(float* d,
                                                 const uint32_t* a,
                                                 uint32_t b0, uint32_t b1) {
    asm volatile(
        "mma.sync.aligned.m16n8k16.row.col.f32.bf16.bf16.f32 "
        "{%0,%1,%2,%3}, {%4,%5,%6,%7}, {%8,%9}, {%0,%1,%2,%3};"
        : "+f"(d[0]), "+f"(d[1]), "+f"(d[2]), "+f"(d[3])
        : "r"(a[0]), "r"(a[1]), "r"(a[2]), "r"(a[3]), "r"(b0), "r"(b1));
}

// Inverse column permutation applied at ldmatrix-address time (computed ONCE).
// sigma (R10): out(b4 b3 b2 b1 b0) = (b4, b1, b3, b2, b0). Here we need
// sigma^-1 on the low 4 bits of the lane row index: x_b1=y_b3, x_b3=y_b2,
// x_b2=y_b1, x_b0=y_b0. Fragment slot (nj,lrow) then holds output column
// sigma^-1(...) matching the R10-proven epilogue layout: thread qi's regs
// from tile pair (2p,2p+1) are output cols 16p + 4*qi + {0,1,2,3}.
static __device__ __forceinline__ uint32_t perm4(uint32_t r) {
    return ((r & 8u) >> 2) | ((r & 4u) << 1) | ((r & 2u) << 1) | (r & 1u);
}

// ---------------- norms kernel (proven) ----------------
__global__ void rbf_norms_kernel(const float* __restrict__ x1,
                                 const float* __restrict__ x2)
{
    int warp = (blockIdx.x * blockDim.x + threadIdx.x) >> 5;
    int lane = threadIdx.x & 31;
    if (warp >= 2 * NROWS) return;
    const float* src = (warp < NROWS) ? x1 : x2;
    float* dst = (warp < NROWS) ? g_n1 : g_n2;
    int row = warp & (NROWS - 1);
    float4 v = reinterpret_cast<const float4*>(src + (size_t)row * KDIM)[lane];
    float s = v.x * v.x + v.y * v.y + v.z * v.z + v.w * v.w;
    #pragma unroll
    for (int m = 16; m > 0; m >>= 1)
        s += __shfl_xor_sync(0xFFFFFFFFu, s, m);
    if (lane == 0) dst[row] = s;
}

// ---------------- main kernel ----------------
__global__ void __launch_bounds__(THREADS)
rbf_mma_kernel(const float* __restrict__ x1,
               const float* __restrict__ x2,
               float* __restrict__ out)
{
    extern __shared__ char smem[];
    uint32_t sbase = smem_u32(smem);
    int tid = threadIdx.x;
    int wid = tid >> 5;
    int lane = tid & 31;

    int rowBase = blockIdx.y * TILE;
    int colBase = blockIdx.x * TILE;

    // ---- load tiles fp32 -> bf16 into padded SMEM (EXACT R4 pattern) ----
    {
        const float4* a4 = reinterpret_cast<const float4*>(x1 + (size_t)rowBase * KDIM);
        const float4* b4 = reinterpret_cast<const float4*>(x2 + (size_t)colBase * KDIM);
        #pragma unroll
        for (int it = 0; it < (TILE * 32) / THREADS; ++it) {
            int idx = tid + it * THREADS;   // 0..4095
            int row = idx >> 5;
            int c4  = idx & 31;             // float4 index within row
            float4 va = a4[(size_t)row * 32 + c4];
            float4 vb = b4[(size_t)row * 32 + c4];
            __nv_bfloat162 a0 = __floats2bfloat162_rn(va.x, va.y);
            __nv_bfloat162 a1 = __floats2bfloat162_rn(va.z, va.w);
            __nv_bfloat162 b0 = __floats2bfloat162_rn(vb.x, vb.y);
            __nv_bfloat162 b1 = __floats2bfloat162_rn(vb.z, vb.w);
            uint32_t off = (uint32_t)row * ROW_BYTES + (uint32_t)c4 * 8;
            *reinterpret_cast<uint2*>(smem + SMEM_A + off) =
                make_uint2(*reinterpret_cast<uint32_t*>(&a0), *reinterpret_cast<uint32_t*>(&a1));
            *reinterpret_cast<uint2*>(smem + SMEM_B + off) =
                make_uint2(*reinterpret_cast<uint32_t*>(&b0), *reinterpret_cast<uint32_t*>(&b1));
        }
        if (tid < TILE) {
            reinterpret_cast<float*>(smem + SMEM_N1)[tid] = g_n1[rowBase + tid];
        } else {
            reinterpret_cast<float*>(smem + SMEM_N2)[tid - TILE] = g_n2[colBase + (tid - TILE)];
        }
    }
    __syncthreads();

    // ---- mma mainloop: warp grid 2(M) x 4(N); each warp 64x32 ----
    int mw = wid >> 2;       // 0..1
    int nw = wid & 3;        // 0..3

    float acc[4][4][4];      // [mi][tile][reg]
    #pragma unroll
    for (int mi = 0; mi < 4; ++mi)
        #pragma unroll
        for (int ni = 0; ni < 4; ++ni)
            #pragma unroll
            for (int r = 0; r < 4; ++r) acc[mi][ni][r] = 0.0f;

    uint32_t lrow  = lane & 15;
    uint32_t lrowB = perm4(lrow);        // one-time permuted B lane row
    uint32_t lhalf = (lane >> 4) * 16;   // byte offset of k-half

    // Per-nj B base addresses (row part fixed across ks)
    uint32_t bAddr0 = sbase + SMEM_B + ((uint32_t)(nw * 32) + lrowB) * ROW_BYTES + lhalf;
    uint32_t bAddr1 = bAddr0 + 16 * ROW_BYTES;

    #pragma unroll
    for (int ks = 0; ks < 8; ++ks) {
        uint32_t koff = (uint32_t)ks * 32;

        uint32_t af[4][4];
        #pragma unroll
        for (int mi = 0; mi < 4; ++mi) {
            uint32_t row = (uint32_t)(mw * 64 + mi * 16) + lrow;
            ldsm_x4(af[mi][0], af[mi][1], af[mi][2], af[mi][3],
                    sbase + SMEM_A + row * ROW_BYTES + lhalf + koff);
        }
        uint32_t bf[2][4];
        ldsm_x4(bf[0][0], bf[0][1], bf[0][2], bf[0][3], bAddr0 + koff);
        ldsm_x4(bf[1][0], bf[1][1], bf[1][2], bf[1][3], bAddr1 + koff);

        #pragma unroll
        for (int mi = 0; mi < 4; ++mi) {
            #pragma unroll
            for (int ni = 0; ni < 4; ++ni) {
                int nj = ni >> 1, sub = ni & 1;
                mma_16816(acc[mi][ni], af[mi], bf[nj][sub], bf[nj][sub + 2]);
            }
        }
    }

    // ---- epilogue (R10-proven): contiguous float4 stores, no shuffles ----
    // Thread (qr = lane>>2, qi = lane&3): tile pair (2p, 2p+1) holds output
    // cols 16p + 4*qi + {0,1,2,3}: regs {a[b], a[b+1], b[b], b[b+1]},
    // b=0 for row qr, b=2 for row qr+8.
    {
        const float* sn1 = reinterpret_cast<const float*>(smem + SMEM_N1);
        const float* sn2 = reinterpret_cast<const float*>(smem + SMEM_N2);
        int qr = lane >> 2;          // 0..7
        int qi = lane & 3;           // 0..3

        float4 n2v[2];
        #pragma unroll
        for (int p = 0; p < 2; ++p)
            n2v[p] = *reinterpret_cast<const float4*>(sn2 + nw * 32 + p * 16 + qi * 4);

        #pragma unroll
        for (int mi = 0; mi < 4; ++mi) {
            int row0 = mw * 64 + mi * 16 + qr;       // rows row0, row0+8
            float n1a = sn1[row0];
            float n1b = sn1[row0 + 8];
            #pragma unroll
            for (int p = 0; p < 2; ++p) {
                int col = nw * 32 + p * 16 + qi * 4;
                const float* a = acc[mi][2 * p];
                const float* b = acc[mi][2 * p + 1];
                float4 oa, ob;
                oa.x = __expf(-GAMMA_F * (n1a + n2v[p].x - 2.0f * a[0]));
                oa.y = __expf(-GAMMA_F * (n1a + n2v[p].y - 2.0f * a[1]));
                oa.z = __expf(-GAMMA_F * (n1a + n2v[p].z - 2.0f * b[0]));
                oa.w = __expf(-GAMMA_F * (n1a + n2v[p].w - 2.0f * b[1]));
                ob.x = __expf(-GAMMA_F * (n1b + n2v[p].x - 2.0f * a[2]));
                ob.y = __expf(-GAMMA_F * (n1b + n2v[p].y - 2.0f * a[3]));
                ob.z = __expf(-GAMMA_F * (n1b + n2v[p].z - 2.0f * b[2]));
                ob.w = __expf(-GAMMA_F * (n1b + n2v[p].w - 2.0f * b[3]));
                *reinterpret_cast<float4*>(
                    out + (size_t)(rowBase + row0) * NROWS + colBase + col) = oa;
                *reinterpret_cast<float4*>(
                    out + (size_t)(rowBase + row0 + 8) * NROWS + colBase + col) = ob;
            }
        }
    }
}

// ---------------- launch ----------------
extern "C" void kernel_launch(void* const* d_in, const int* in_sizes, int n_in,
                              void* d_out, int out_size)
{
    const float* x1 = (const float*)d_in[0];
    const float* x2 = (const float*)d_in[1];
    float* out = (float*)d_out;

    cudaFuncSetAttribute(rbf_mma_kernel,
                         cudaFuncAttributeMaxDynamicSharedMemorySize, SMEM_TOTAL);
    cudaFuncSetAttribute(rbf_mma_kernel,
                         cudaFuncAttributePreferredSharedMemoryCarveout, 100);

    rbf_norms_kernel<<<(2 * NROWS) / 8, 256>>>(x1, x2);

    dim3 grid(NROWS / TILE, NROWS / TILE);   // 64 x 64
    rbf_mma_kernel<<<grid, THREADS, SMEM_TOTAL>>>(x1, x2, out);
}

// round 14
// speedup vs baseline: 1.3466x; 1.2405x over previous
#include <cuda_runtime.h>
#include <cuda_bf16.h>
#include <cstdint>

#define NROWS 8192
#define KDIM  128
#define GAMMA_F 0.005f   // 1/(2*10^2)

#define TILE 128
#define THREADS 256

// SMEM: padded bf16 tiles, row stride 272 bytes (128 bf16 = 256B + 16B pad)
#define ROW_BYTES 272
#define TILE_BYTES (TILE * ROW_BYTES)          // 34816
#define SMEM_A  0
#define SMEM_B  TILE_BYTES                      // 34816
#define SMEM_N1 (2 * TILE_BYTES)                // 69632
#define SMEM_N2 (SMEM_N1 + TILE * 4)            // 70144
#define SMEM_TOTAL (SMEM_N2 + TILE * 4)         // 70656

__device__ float g_n1[NROWS];
__device__ float g_n2[NROWS];
__device__ __nv_bfloat16 g_x1b[NROWS * KDIM];   // 2 MB
__device__ __nv_bfloat16 g_x2b[NROWS * KDIM];   // 2 MB

static __device__ __forceinline__ uint32_t smem_u32(const void* p) {
    uint32_t a;
    asm("{ .reg .u64 t; cvta.to.shared.u64 t, %1; cvt.u32.u64 %0, t; }"
        : "=r"(a) : "l"(p));
    return a;
}

static __device__ __forceinline__ void cp_async16(uint32_t smem_addr, const void* gptr) {
    asm volatile("cp.async.cg.shared.global [%0], [%1], 16;"
                 :: "r"(smem_addr), "l"(gptr) : "memory");
}
static __device__ __forceinline__ void cp_async_commit_wait() {
    asm volatile("cp.async.commit_group;" ::: "memory");
    asm volatile("cp.async.wait_group 0;" ::: "memory");
}

static __device__ __forceinline__ void ldsm_x4(uint32_t& r0, uint32_t& r1,
                                               uint32_t& r2, uint32_t& r3,
                                               uint32_t addr) {
    asm volatile("ldmatrix.sync.aligned.m8n8.x4.shared.b16 {%0,%1,%2,%3}, [%4];"
                 : "=r"(r0), "=r"(r1), "=r"(r2), "=r"(r3) : "r"(addr));
}

static __device__ __forceinline__ void mma_16816(float* d,
                                                 const uint32_t* a,
                                                 uint32_t b0, uint32_t b1) {
    asm volatile(
        "mma.sync.aligned.m16n8k16.row.col.f32.bf16.bf16.f32 "
        "{%0,%1,%2,%3}, {%4,%5,%6,%7}, {%8,%9}, {%0,%1,%2,%3};"
        : "+f"(d[0]), "+f"(d[1]), "+f"(d[2]), "+f"(d[3])
        : "r"(a[0]), "r"(a[1]), "r"(a[2]), "r"(a[3]), "r"(b0), "r"(b1));
}

// ---------------- prep kernel: norms + fp32->bf16 conversion ----------------
// One warp per row. Norm reduction identical to the proven norms kernel;
// bf16 conversion identical to R4's in-kernel conversion -> bitwise-same output.
__global__ void rbf_prep_kernel(const float* __restrict__ x1,
                                const float* __restrict__ x2)
{
    int warp = (blockIdx.x * blockDim.x + threadIdx.x) >> 5;
    int lane = threadIdx.x & 31;
    if (warp >= 2 * NROWS) return;
    const float* src = (warp < NROWS) ? x1 : x2;
    float* dstn = (warp < NROWS) ? g_n1 : g_n2;
    __nv_bfloat16* dstb = (warp < NROWS) ? g_x1b : g_x2b;
    int row = warp & (NROWS - 1);

    float4 v = reinterpret_cast<const float4*>(src + (size_t)row * KDIM)[lane];
    float s = v.x * v.x + v.y * v.y + v.z * v.z + v.w * v.w;
    #pragma unroll
    for (int m = 16; m > 0; m >>= 1)
        s += __shfl_xor_sync(0xFFFFFFFFu, s, m);
    if (lane == 0) dstn[row] = s;

    __nv_bfloat162 p0 = __floats2bfloat162_rn(v.x, v.y);
    __nv_bfloat162 p1 = __floats2bfloat162_rn(v.z, v.w);
    reinterpret_cast<uint2*>(dstb + (size_t)row * KDIM)[lane] =
        make_uint2(*reinterpret_cast<uint32_t*>(&p0), *reinterpret_cast<uint32_t*>(&p1));
}

// ---------------- main kernel (R4 mainloop/epilogue + cp.async loads) -------
__global__ void __launch_bounds__(THREADS)
rbf_mma_kernel(const float* __restrict__ x1,
               const float* __restrict__ x2,
               float* __restrict__ out)
{
    extern __shared__ char smem[];
    uint32_t sbase = smem_u32(smem);
    int tid = threadIdx.x;
    int wid = tid >> 5;
    int lane = tid & 31;

    int rowBase = blockIdx.y * TILE;
    int colBase = blockIdx.x * TILE;

    // ---- async tile loads: bf16 GMEM -> padded SMEM, no registers, no L1 ----
    {
        const char* aG = reinterpret_cast<const char*>(g_x1b + (size_t)rowBase * KDIM);
        const char* bG = reinterpret_cast<const char*>(g_x2b + (size_t)colBase * KDIM);
        // 128 rows x 16 chunks of 16B per tile; idx = row*16 + chunk
        #pragma unroll
        for (int it = 0; it < 8; ++it) {
            int idx = tid + it * THREADS;           // 0..2047
            int row = idx >> 4;
            int ch  = idx & 15;
            uint32_t off = (uint32_t)row * ROW_BYTES + (uint32_t)ch * 16;
            cp_async16(sbase + SMEM_A + off, aG + (size_t)idx * 16);
            cp_async16(sbase + SMEM_B + off, bG + (size_t)idx * 16);
        }
        // stage norms with regular loads (independent of cp.async groups)
        if (tid < TILE) {
            reinterpret_cast<float*>(smem + SMEM_N1)[tid] = g_n1[rowBase + tid];
        } else {
            reinterpret_cast<float*>(smem + SMEM_N2)[tid - TILE] = g_n2[colBase + (tid - TILE)];
        }
        cp_async_commit_wait();
    }
    __syncthreads();

    // ---- mma mainloop: warp grid 2(M) x 4(N); each warp 64x32 (R4 exact) ----
    int mw = wid >> 2;       // 0..1
    int nw = wid & 3;        // 0..3

    float acc[4][4][4];      // [mi][ni][reg]
    #pragma unroll
    for (int mi = 0; mi < 4; ++mi)
        #pragma unroll
        for (int ni = 0; ni < 4; ++ni)
            #pragma unroll
            for (int r = 0; r < 4; ++r) acc[mi][ni][r] = 0.0f;

    uint32_t lrow  = lane & 15;
    uint32_t lhalf = (lane >> 4) * 16;   // byte offset of k-half

    #pragma unroll
    for (int ks = 0; ks < 8; ++ks) {
        uint32_t koff = (uint32_t)ks * 32 + lhalf;

        uint32_t af[4][4];
        #pragma unroll
        for (int mi = 0; mi < 4; ++mi) {
            uint32_t row = (uint32_t)(mw * 64 + mi * 16) + lrow;
            ldsm_x4(af[mi][0], af[mi][1], af[mi][2], af[mi][3],
                    sbase + SMEM_A + row * ROW_BYTES + koff);
        }
        uint32_t bf[2][4];
        #pragma unroll
        for (int nj = 0; nj < 2; ++nj) {
            uint32_t row = (uint32_t)(nw * 32 + nj * 16) + lrow;
            ldsm_x4(bf[nj][0], bf[nj][1], bf[nj][2], bf[nj][3],
                    sbase + SMEM_B + row * ROW_BYTES + koff);
        }
        #pragma unroll
        for (int mi = 0; mi < 4; ++mi) {
            #pragma unroll
            for (int ni = 0; ni < 4; ++ni) {
                int nj = ni >> 1, sub = ni & 1;
                mma_16816(acc[mi][ni], af[mi], bf[nj][sub], bf[nj][sub + 2]);
            }
        }
    }

    // ---- R4 epilogue: exp directly on acc, STG.64, no cross-lane deps ----
    {
        const float* sn1 = reinterpret_cast<const float*>(smem + SMEM_N1);
        const float* sn2 = reinterpret_cast<const float*>(smem + SMEM_N2);
        int qr = lane >> 2;          // 0..7
        int qc = (lane & 3) * 2;     // 0,2,4,6

        #pragma unroll
        for (int mi = 0; mi < 4; ++mi) {
            int row0 = mw * 64 + mi * 16 + qr;       // rows row0 and row0+8
            float n1a = sn1[row0];
            float n1b = sn1[row0 + 8];
            float* out0 = out + (size_t)(rowBase + row0) * NROWS + colBase;
            float* out1 = out0 + (size_t)8 * NROWS;
            #pragma unroll
            for (int ni = 0; ni < 4; ++ni) {
                int col = nw * 32 + ni * 8 + qc;
                float n2a = sn2[col];
                float n2b = sn2[col + 1];
                float2 oa, ob;
                oa.x = __expf(-GAMMA_F * (n1a + n2a - 2.0f * acc[mi][ni][0]));
                oa.y = __expf(-GAMMA_F * (n1a + n2b - 2.0f * acc[mi][ni][1]));
                ob.x = __expf(-GAMMA_F * (n1b + n2a - 2.0f * acc[mi][ni][2]));
                ob.y = __expf(-GAMMA_F * (n1b + n2b - 2.0f * acc[mi][ni][3]));
                *reinterpret_cast<float2*>(out0 + col) = oa;
                *reinterpret_cast<float2*>(out1 + col) = ob;
            }
        }
    }
}

// ---------------- launch ----------------
extern "C" void kernel_launch(void* const* d_in, const int* in_sizes, int n_in,
                              void* d_out, int out_size)
{
    const float* x1 = (const float*)d_in[0];
    const float* x2 = (const float*)d_in[1];
    float* out = (float*)d_out;

    cudaFuncSetAttribute(rbf_mma_kernel,
                         cudaFuncAttributeMaxDynamicSharedMemorySize, SMEM_TOTAL);
    cudaFuncSetAttribute(rbf_mma_kernel,
                         cudaFuncAttributePreferredSharedMemoryCarveout, 100);

    // prep: norms + bf16 conversion (16384 warps, 8 warps/block)
    rbf_prep_kernel<<<(2 * NROWS) / 8, 256>>>(x1, x2);

    dim3 grid(NROWS / TILE, NROWS / TILE);   // 64 x 64
    rbf_mma_kernel<<<grid, THREADS, SMEM_TOTAL>>>(x1, x2, out);
}

// round 15
// speedup vs baseline: 1.3530x; 1.0048x over previous
#include <cuda_runtime.h>
#include <cuda_bf16.h>
#include <cstdint>

#define NROWS 8192
#define KDIM  128
#define GAMMA_F 0.005f   // 1/(2*10^2)

#define TILE 128
#define THREADS 256

// SMEM: padded bf16 tiles, row stride 272 bytes (128 bf16 = 256B + 16B pad)
#define ROW_BYTES 272
#define TILE_BYTES (TILE * ROW_BYTES)          // 34816
#define SMEM_A  0
#define SMEM_B  TILE_BYTES                      // 34816
#define SMEM_N1 (2 * TILE_BYTES)                // 69632
#define SMEM_N2 (SMEM_N1 + TILE * 4)            // 70144
#define SMEM_TOTAL (SMEM_N2 + TILE * 4)         // 70656

__device__ float g_n1[NROWS];
__device__ float g_n2[NROWS];
__device__ __nv_bfloat16 g_x1b[NROWS * KDIM];   // 2 MB
__device__ __nv_bfloat16 g_x2b[NROWS * KDIM];   // 2 MB

static __device__ __forceinline__ uint32_t smem_u32(const void* p) {
    uint32_t a;
    asm("{ .reg .u64 t; cvta.to.shared.u64 t, %1; cvt.u32.u64 %0, t; }"
        : "=r"(a) : "l"(p));
    return a;
}

static __device__ __forceinline__ void cp_async16(uint32_t smem_addr, const void* gptr) {
    asm volatile("cp.async.cg.shared.global [%0], [%1], 16;"
                 :: "r"(smem_addr), "l"(gptr) : "memory");
}
static __device__ __forceinline__ void cp_async_commit_wait() {
    asm volatile("cp.async.commit_group;" ::: "memory");
    asm volatile("cp.async.wait_group 0;" ::: "memory");
}

static __device__ __forceinline__ void ldsm_x4(uint32_t& r0, uint32_t& r1,
                                               uint32_t& r2, uint32_t& r3,
                                               uint32_t addr) {
    asm volatile("ldmatrix.sync.aligned.m8n8.x4.shared.b16 {%0,%1,%2,%3}, [%4];"
                 : "=r"(r0), "=r"(r1), "=r"(r2), "=r"(r3) : "r"(addr));
}

static __device__ __forceinline__ void mma_16816(float* d,
                                                 const uint32_t* a,
                                                 uint32_t b0, uint32_t b1) {
    asm volatile(
        "mma.sync.aligned.m16n8k16.row.col.f32.bf16.bf16.f32 "
        "{%0,%1,%2,%3}, {%4,%5,%6,%7}, {%8,%9}, {%0,%1,%2,%3};"
        : "+f"(d[0]), "+f"(d[1]), "+f"(d[2]), "+f"(d[3])
        : "r"(a[0]), "r"(a[1]), "r"(a[2]), "r"(a[3]), "r"(b0), "r"(b1));
}

// Inverse column permutation applied at ldmatrix-address time (computed ONCE
// per thread, R13-proven). Fragment slot (nj,lrow) holds output column such
// that thread qi's regs from tile pair (2p,2p+1) are cols 16p+4qi+{0,1,2,3}.
static __device__ __forceinline__ uint32_t perm4(uint32_t r) {
    return ((r & 8u) >> 2) | ((r & 4u) << 1) | ((r & 2u) << 1) | (r & 1u);
}

// ---------------- prep kernel: norms + fp32->bf16 conversion ----------------
__global__ void rbf_prep_kernel(const float* __restrict__ x1,
                                const float* __restrict__ x2)
{
    int warp = (blockIdx.x * blockDim.x + threadIdx.x) >> 5;
    int lane = threadIdx.x & 31;
    if (warp >= 2 * NROWS) return;
    const float* src = (warp < NROWS) ? x1 : x2;
    float* dstn = (warp < NROWS) ? g_n1 : g_n2;
    __nv_bfloat16* dstb = (warp < NROWS) ? g_x1b : g_x2b;
    int row = warp & (NROWS - 1);

    float4 v = reinterpret_cast<const float4*>(src + (size_t)row * KDIM)[lane];
    float s = v.x * v.x + v.y * v.y + v.z * v.z + v.w * v.w;
    #pragma unroll
    for (int m = 16; m > 0; m >>= 1)
        s += __shfl_xor_sync(0xFFFFFFFFu, s, m);
    if (lane == 0) dstn[row] = s;

    __nv_bfloat162 p0 = __floats2bfloat162_rn(v.x, v.y);
    __nv_bfloat162 p1 = __floats2bfloat162_rn(v.z, v.w);
    reinterpret_cast<uint2*>(dstb + (size_t)row * KDIM)[lane] =
        make_uint2(*reinterpret_cast<uint32_t*>(&p0), *reinterpret_cast<uint32_t*>(&p1));
}

// ---------------- main kernel: cp.async loads + permuted-B + STG.128 --------
__global__ void __launch_bounds__(THREADS)
rbf_mma_kernel(const float* __restrict__ x1,
               const float* __restrict__ x2,
               float* __restrict__ out)
{
    extern __shared__ char smem[];
    uint32_t sbase = smem_u32(smem);
    int tid = threadIdx.x;
    int wid = tid >> 5;
    int lane = tid & 31;

    int rowBase = blockIdx.y * TILE;
    int colBase = blockIdx.x * TILE;

    // ---- async tile loads: bf16 GMEM -> padded SMEM (R14 exact) ----
    {
        const char* aG = reinterpret_cast<const char*>(g_x1b + (size_t)rowBase * KDIM);
        const char* bG = reinterpret_cast<const char*>(g_x2b + (size_t)colBase * KDIM);
        #pragma unroll
        for (int it = 0; it < 8; ++it) {
            int idx = tid + it * THREADS;           // 0..2047
            int row = idx >> 4;
            int ch  = idx & 15;
            uint32_t off = (uint32_t)row * ROW_BYTES + (uint32_t)ch * 16;
            cp_async16(sbase + SMEM_A + off, aG + (size_t)idx * 16);
            cp_async16(sbase + SMEM_B + off, bG + (size_t)idx * 16);
        }
        if (tid < TILE) {
            reinterpret_cast<float*>(smem + SMEM_N1)[tid] = g_n1[rowBase + tid];
        } else {
            reinterpret_cast<float*>(smem + SMEM_N2)[tid - TILE] = g_n2[colBase + (tid - TILE)];
        }
        cp_async_commit_wait();
    }
    __syncthreads();

    // ---- mma mainloop: warp grid 2(M) x 4(N); each warp 64x32 ----
    int mw = wid >> 2;       // 0..1
    int nw = wid & 3;        // 0..3

    float acc[4][4][4];      // [mi][tile][reg]
    #pragma unroll
    for (int mi = 0; mi < 4; ++mi)
        #pragma unroll
        for (int ni = 0; ni < 4; ++ni)
            #pragma unroll
            for (int r = 0; r < 4; ++r) acc[mi][ni][r] = 0.0f;

    uint32_t lrow  = lane & 15;
    uint32_t lrowB = perm4(lrow);        // one-time permuted B lane row
    uint32_t lhalf = (lane >> 4) * 16;   // byte offset of k-half

    uint32_t bAddr0 = sbase + SMEM_B + ((uint32_t)(nw * 32) + lrowB) * ROW_BYTES + lhalf;
    uint32_t bAddr1 = bAddr0 + 16 * ROW_BYTES;

    #pragma unroll
    for (int ks = 0; ks < 8; ++ks) {
        uint32_t koff = (uint32_t)ks * 32;

        uint32_t af[4][4];
        #pragma unroll
        for (int mi = 0; mi < 4; ++mi) {
            uint32_t row = (uint32_t)(mw * 64 + mi * 16) + lrow;
            ldsm_x4(af[mi][0], af[mi][1], af[mi][2], af[mi][3],
                    sbase + SMEM_A + row * ROW_BYTES + lhalf + koff);
        }
        uint32_t bf[2][4];
        ldsm_x4(bf[0][0], bf[0][1], bf[0][2], bf[0][3], bAddr0 + koff);
        ldsm_x4(bf[1][0], bf[1][1], bf[1][2], bf[1][3], bAddr1 + koff);

        #pragma unroll
        for (int mi = 0; mi < 4; ++mi) {
            #pragma unroll
            for (int ni = 0; ni < 4; ++ni) {
                int nj = ni >> 1, sub = ni & 1;
                mma_16816(acc[mi][ni], af[mi], bf[nj][sub], bf[nj][sub + 2]);
            }
        }
    }

    // ---- epilogue (R10/R13-proven): contiguous float4 stores, no shuffles ----
    {
        const float* sn1 = reinterpret_cast<const float*>(smem + SMEM_N1);
        const float* sn2 = reinterpret_cast<const float*>(smem + SMEM_N2);
        int qr = lane >> 2;          // 0..7
        int qi = lane & 3;           // 0..3

        float4 n2v[2];
        #pragma unroll
        for (int p = 0; p < 2; ++p)
            n2v[p] = *reinterpret_cast<const float4*>(sn2 + nw * 32 + p * 16 + qi * 4);

        #pragma unroll
        for (int mi = 0; mi < 4; ++mi) {
            int row0 = mw * 64 + mi * 16 + qr;       // rows row0, row0+8
            float n1a = sn1[row0];
            float n1b = sn1[row0 + 8];
            #pragma unroll
            for (int p = 0; p < 2; ++p) {
                int col = nw * 32 + p * 16 + qi * 4;
                const float* a = acc[mi][2 * p];
                const float* b = acc[mi][2 * p + 1];
                float4 oa, ob;
                oa.x = __expf(-GAMMA_F * (n1a + n2v[p].x - 2.0f * a[0]));
                oa.y = __expf(-GAMMA_F * (n1a + n2v[p].y - 2.0f * a[1]));
                oa.z = __expf(-GAMMA_F * (n1a + n2v[p].z - 2.0f * b[0]));
                oa.w = __expf(-GAMMA_F * (n1a + n2v[p].w - 2.0f * b[1]));
                ob.x = __expf(-GAMMA_F * (n1b + n2v[p].x - 2.0f * a[2]));
                ob.y = __expf(-GAMMA_F * (n1b + n2v[p].y - 2.0f * a[3]));
                ob.z = __expf(-GAMMA_F * (n1b + n2v[p].z - 2.0f * b[2]));
                ob.w = __expf(-GAMMA_F * (n1b + n2v[p].w - 2.0f * b[3]));
                *reinterpret_cast<float4*>(
                    out + (size_t)(rowBase + row0) * NROWS + colBase + col) = oa;
                *reinterpret_cast<float4*>(
                    out + (size_t)(rowBase + row0 + 8) * NROWS + colBase + col) = ob;
            }
        }
    }
}

// ---------------- launch ----------------
extern "C" void kernel_launch(void* const* d_in, const int* in_sizes, int n_in,
                              void* d_out, int out_size)
{
    const float* x1 = (const float*)d_in[0];
    const float* x2 = (const float*)d_in[1];
    float* out = (float*)d_out;

    cudaFuncSetAttribute(rbf_mma_kernel,
                         cudaFuncAttributeMaxDynamicSharedMemorySize, SMEM_TOTAL);
    cudaFuncSetAttribute(rbf_mma_kernel,
                         cudaFuncAttributePreferredSharedMemoryCarveout, 100);

    rbf_prep_kernel<<<(2 * NROWS) / 8, 256>>>(x1, x2);

    dim3 grid(NROWS / TILE, NROWS / TILE);   // 64 x 64
    rbf_mma_kernel<<<grid, THREADS, SMEM_TOTAL>>>(x1, x2, out);
}